// round 6
// baseline (speedup 1.0000x reference)
#include <cuda_runtime.h>

#define TT 512
#define BB 64
#define II 1024
#define HH 1024
#define UPITCH 1026   // padded smem pitch (floats)

// h3 exchange buffer, [parity][h-index][b]; b contiguous for coalesced staging
__device__ float g_h3[2][HH][BB];
// row-scoped barrier state: 4 rows, padded 128B apart; self-resetting
__device__ unsigned int g_cnt4[4 * 32];
__device__ unsigned int g_ack4[4 * 32];
__device__ volatile unsigned int g_flag4[4 * 32];

__device__ __forceinline__ unsigned long long pk2(float lo, float hi) {
    unsigned long long r;
    asm("mov.b64 %0, {%1, %2};" : "=l"(r) : "f"(lo), "f"(hi));
    return r;
}
__device__ __forceinline__ unsigned long long ffma2(unsigned long long a,
                                                    unsigned long long b,
                                                    unsigned long long c) {
    unsigned long long d;
    asm("fma.rn.f32x2 %0, %1, %2, %3;" : "=l"(d) : "l"(a), "l"(b), "l"(c));
    return d;
}
__device__ __forceinline__ float psum(unsigned long long p) {
    float lo = __uint_as_float((unsigned int)(p & 0xFFFFFFFFull));
    float hi = __uint_as_float((unsigned int)(p >> 32));
    return lo + hi;
}
__device__ __forceinline__ void st_pair4(float* p, float4 v) {
    *(unsigned long long*)(p)     = pk2(v.x, v.y);
    *(unsigned long long*)(p + 2) = pk2(v.z, v.w);
}

// ---------------------------------------------------------------------------
// xw = x @ W^T + bW  (M=32768, N=1024, K=1024) -> d_out.
// Double-buffered smem: ONE __syncthreads per 16-k chunk; STS for chunk n+1
// overlaps compute of chunk n.
// ---------------------------------------------------------------------------
__global__ __launch_bounds__(256, 1)
void gemm_xw_kernel(const float* __restrict__ X, const float* __restrict__ W,
                    const float* __restrict__ bW, float* __restrict__ C) {
    __shared__ float xs[2][128][18];
    __shared__ float ws[2][128][18];

    const int tid = threadIdx.x;
    const int m0 = blockIdx.y * 128;
    const int n0 = blockIdx.x * 128;
    const int tm = tid & 15;
    const int tn = tid >> 4;
    const int lr = tid >> 2;
    const int lc = (tid & 3) << 2;

    const float* xg = X + (size_t)(m0 + lr) * II + lc;
    const float* wg = W + (size_t)(n0 + lr) * II + lc;

    unsigned long long acc[8][8];
#pragma unroll
    for (int i = 0; i < 8; i++)
#pragma unroll
        for (int j = 0; j < 8; j++) acc[i][j] = 0ull;

    // preload chunk 0 into buffer 0
    {
        const float4 xa = *(const float4*)(xg);
        const float4 xb = *(const float4*)(xg + 64 * II);
        const float4 wa = *(const float4*)(wg);
        const float4 wb = *(const float4*)(wg + 64 * II);
        st_pair4(&xs[0][lr][lc], xa);
        st_pair4(&xs[0][lr + 64][lc], xb);
        st_pair4(&ws[0][lr][lc], wa);
        st_pair4(&ws[0][lr + 64][lc], wb);
    }
    __syncthreads();

    int pb = 0;
    for (int k0 = 0; k0 < II; k0 += 16) {
        const bool more = (k0 + 16 < II);
        float4 nxa, nxb, nwa, nwb;
        if (more) {               // issue next-chunk LDGs first (hidden by compute)
            nxa = *(const float4*)(xg + k0 + 16);
            nxb = *(const float4*)(xg + 64 * II + k0 + 16);
            nwa = *(const float4*)(wg + k0 + 16);
            nwb = *(const float4*)(wg + 64 * II + k0 + 16);
        }
#pragma unroll
        for (int kp = 0; kp < 8; kp++) {
            unsigned long long af[8], bf[8];
#pragma unroll
            for (int i = 0; i < 8; i++)
                af[i] = *(const unsigned long long*)&xs[pb][tm + 16 * i][kp * 2];
#pragma unroll
            for (int j = 0; j < 8; j++)
                bf[j] = *(const unsigned long long*)&ws[pb][tn + 16 * j][kp * 2];
#pragma unroll
            for (int i = 0; i < 8; i++)
#pragma unroll
                for (int j = 0; j < 8; j++)
                    acc[i][j] = ffma2(af[i], bf[j], acc[i][j]);
        }
        if (more) {               // store into the OTHER buffer; readers use pb
            st_pair4(&xs[pb ^ 1][lr][lc], nxa);
            st_pair4(&xs[pb ^ 1][lr + 64][lc], nxb);
            st_pair4(&ws[pb ^ 1][lr][lc], nwa);
            st_pair4(&ws[pb ^ 1][lr + 64][lc], nwb);
        }
        __syncthreads();
        pb ^= 1;
    }

#pragma unroll
    for (int i = 0; i < 8; i++) {
        const int m = m0 + tm + 16 * i;
#pragma unroll
        for (int j = 0; j < 8; j++) {
            const int n = n0 + tn + 16 * j;
            C[(size_t)m * HH + n] = psum(acc[i][j]) + bW[n];
        }
    }
}

// ---------------------------------------------------------------------------
// Persistent recurrence. 128 CTAs = 4(b) x 32(c) tiles of 16b x 32c.
// Row-scoped SELF-RESETTING barriers (replay-safe: every launch starts from
// cnt=0, ack=0, flag=0 and restores that state before exit).
// ---------------------------------------------------------------------------
__global__ __launch_bounds__(256, 1)
void rnn_steps_kernel(const float* __restrict__ U, const float* __restrict__ bU,
                      float* __restrict__ out) {
    extern __shared__ float fsmem[];
    float* Usm = fsmem;                  // 32 * UPITCH
    float* Hsm = fsmem + 32 * UPITCH;    // 16 * UPITCH
    float* red = fsmem + 48 * UPITCH;    // 8 * 512

    const int tid = threadIdx.x;
    const int cgid = blockIdx.x & 31;
    const int bgid = blockIdx.x >> 5;
    const int c0 = cgid * 32;
    const int b0 = bgid * 16;
    const int bslot = bgid * 32;

    for (int idx = tid; idx < 32 * 1024; idx += 256) {
        const int r = idx >> 10, k = idx & 1023;
        Usm[r * UPITCH + k] = U[(size_t)(c0 + r) * HH + k];
    }

    const int o0 = 2 * tid;
    const int blo = o0 >> 5;
    const int clo = o0 & 31;
    const int b = b0 + blo;
    const int c = c0 + clo;
    const float bu0 = bU[c];
    const float bu1 = bU[c + 1];

    const int w = tid >> 5;
    const int lane = tid & 31;
    const int bg = lane & 3;
    const int cg = lane >> 2;
    const int kb1 = w * 64;
    const int kb2 = 512 + w * 64;

    const int sg = tid & 3;
    const int sk = tid >> 2;

    __syncthreads();

    // t = 0 : h3(0) = tanh(xw_0)
    {
        const size_t idx = ((size_t)b * TT) * HH + c;
        const float2 xw = *(const float2*)&out[idx];
        const float h0 = tanhf(xw.x);
        const float h1 = tanhf(xw.y);
        out[idx] = h0;
        out[idx + 1] = h1;
        g_h3[0][c][b] = h0;
        g_h3[0][c + 1][b] = h1;
    }
    __threadfence();
    __syncthreads();
    if (tid == 0) {
        if (atomicAdd(&g_cnt4[bslot], 1) == 31) {
            g_cnt4[bslot] = 0;
            __threadfence();
            g_flag4[bslot] = 1;
        } else {
            while (g_flag4[bslot] < 1u) { }
        }
    }
    __syncthreads();

    for (int t = 0; t < TT - 1; t++) {
        const int par = t & 1;
        const size_t nidx = ((size_t)b * TT + (t + 1)) * HH + c;
        const float2 xwn = *(const float2*)&out[nidx];
        const float* hb = &g_h3[par][0][0];

        // stage half0 (k < 512)
        {
            float4 v[8];
#pragma unroll
            for (int it = 0; it < 8; it++) {
                const int k = sk + 64 * it;
                v[it] = __ldcg((const float4*)(hb + (size_t)k * BB + b0 + 4 * sg));
            }
#pragma unroll
            for (int it = 0; it < 8; it++) {
                const int k = sk + 64 * it;
                float* dst = Hsm + k;
                dst[(4 * sg + 0) * UPITCH] = v[it].x;
                dst[(4 * sg + 1) * UPITCH] = v[it].y;
                dst[(4 * sg + 2) * UPITCH] = v[it].z;
                dst[(4 * sg + 3) * UPITCH] = v[it].w;
            }
        }
        __syncthreads();

        // issue half1 LDGs, hidden under pass1
        float4 v1[8];
#pragma unroll
        for (int it = 0; it < 8; it++) {
            const int k = 512 + sk + 64 * it;
            v1[it] = __ldcg((const float4*)(hb + (size_t)k * BB + b0 + 4 * sg));
        }

        unsigned long long acc[4][4];
#pragma unroll
        for (int i = 0; i < 4; i++)
#pragma unroll
            for (int q = 0; q < 4; q++) acc[i][q] = 0ull;

#pragma unroll 8
        for (int kp = 0; kp < 32; kp++) {
            const int k0 = kb1 + 2 * kp;
            unsigned long long a[4], u[4];
#pragma unroll
            for (int i = 0; i < 4; i++)
                a[i] = *(const unsigned long long*)&Hsm[(i * 4 + bg) * UPITCH + k0];
#pragma unroll
            for (int q = 0; q < 4; q++)
                u[q] = *(const unsigned long long*)&Usm[(q * 8 + cg) * UPITCH + k0];
#pragma unroll
            for (int i = 0; i < 4; i++)
#pragma unroll
                for (int q = 0; q < 4; q++)
                    acc[i][q] = ffma2(a[i], u[q], acc[i][q]);
        }

#pragma unroll
        for (int it = 0; it < 8; it++) {
            const int k = 512 + sk + 64 * it;
            float* dst = Hsm + k;
            dst[(4 * sg + 0) * UPITCH] = v1[it].x;
            dst[(4 * sg + 1) * UPITCH] = v1[it].y;
            dst[(4 * sg + 2) * UPITCH] = v1[it].z;
            dst[(4 * sg + 3) * UPITCH] = v1[it].w;
        }
        __syncthreads();

#pragma unroll 8
        for (int kp = 0; kp < 32; kp++) {
            const int k0 = kb2 + 2 * kp;
            unsigned long long a[4], u[4];
#pragma unroll
            for (int i = 0; i < 4; i++)
                a[i] = *(const unsigned long long*)&Hsm[(i * 4 + bg) * UPITCH + k0];
#pragma unroll
            for (int q = 0; q < 4; q++)
                u[q] = *(const unsigned long long*)&Usm[(q * 8 + cg) * UPITCH + k0];
#pragma unroll
            for (int i = 0; i < 4; i++)
#pragma unroll
                for (int q = 0; q < 4; q++)
                    acc[i][q] = ffma2(a[i], u[q], acc[i][q]);
        }

#pragma unroll
        for (int i = 0; i < 4; i++) {
            const int ob = (i * 4 + bg) * 32;
#pragma unroll
            for (int q = 0; q < 4; q++)
                red[w * 512 + ob + q * 8 + cg] = psum(acc[i][q]);
        }
        __syncthreads();

        float s0 = bu0, s1 = bu1;
#pragma unroll
        for (int ww = 0; ww < 8; ww++) {
            const float2 p = *(const float2*)&red[ww * 512 + o0];
            s0 += p.x;
            s1 += p.y;
        }

        const float h0 = tanhf(xwn.x + s0);
        const float h1 = tanhf(xwn.y + s1);
        out[nidx] = h0;
        out[nidx + 1] = h1;
        const int par1 = par ^ 1;
        g_h3[par1][c][b] = h0;
        g_h3[par1][c + 1][b] = h1;

        if (t == TT - 2) {
            const size_t o2 = (size_t)BB * TT * HH + (size_t)b * HH + c;
            out[o2] = h0;
            out[o2 + 1] = h1;
            break;
        }

        __threadfence();
        __syncthreads();
        if (tid == 0) {
            const unsigned int target = (unsigned int)(t + 2);
            if (atomicAdd(&g_cnt4[bslot], 1) == 31) {
                g_cnt4[bslot] = 0;
                __threadfence();
                g_flag4[bslot] = target;
            } else {
                while (g_flag4[bslot] < target) { }
            }
        }
        __syncthreads();
    }

    // ---- replay-safe teardown: final row barrier, then ack'd reset ----
    __syncthreads();
    if (tid == 0) {
        const unsigned int target = (unsigned int)TT;   // 512, beyond loop targets
        if (atomicAdd(&g_cnt4[bslot], 1) == 31) {
            g_cnt4[bslot] = 0;
            __threadfence();
            g_flag4[bslot] = target;
        } else {
            while (g_flag4[bslot] < target) { }
        }
        // every row CTA has now OBSERVED flag==512; last acker resets flag.
        if (atomicAdd(&g_ack4[bslot], 1) == 31) {
            g_ack4[bslot] = 0;
            g_flag4[bslot] = 0;     // next launch starts from pristine state
            __threadfence();
        }
    }
}

extern "C" void kernel_launch(void* const* d_in, const int* in_sizes, int n_in,
                              void* d_out, int out_size) {
    const float* x  = (const float*)d_in[0];
    const float* W  = (const float*)d_in[1];
    const float* bW = (const float*)d_in[2];
    const float* U  = (const float*)d_in[3];
    const float* bU = (const float*)d_in[4];
    float* out = (float*)d_out;

    const int rnn_smem = (48 * UPITCH + 8 * 512) * sizeof(float);
    cudaFuncSetAttribute(rnn_steps_kernel,
                         cudaFuncAttributeMaxDynamicSharedMemorySize, rnn_smem);

    dim3 ggrid(HH / 128, (BB * TT) / 128);  // (8, 256)
    gemm_xw_kernel<<<ggrid, 256>>>(x, W, bW, out);

    rnn_steps_kernel<<<128, 256, rnn_smem>>>(U, bU, out);
}